// round 14
// baseline (speedup 1.0000x reference)
#include <cuda_runtime.h>

// out[b,f] = x[b,f] * (log_sigma[f] < 1.0f ? e : 1.0f)
// BATCH=65536, N_FEATURES=4096 -> 2^25 v8 (256-bit) elements. HBM stream.
//
// R14: champion mechanism (fine-grained, 1024-thr blocks, batch-depth-2
// front-batched loads) with 256-bit ld/st (sm_100+): 2 x v8 per thread,
// 16384 blocks. Same load-batch depth as the 89% champion, but 64B/lane
// in flight and half the LSU instructions / half the CTAs.
// Discriminates bytes-in-flight vs batch-depth as the MLP4 regression cause.

#define N_FEATURES  4096
#define V8_PER_ROW  (N_FEATURES / 8)             // 512, power of two
#define TOTAL_V8    (65536LL * V8_PER_ROW)       // 2^25

#define THREADS  1024
#define BLOCKS   16384                            // 2^24 threads
#define NSTRIDE  ((long long)THREADS * BLOCKS)    // 2^24, multiple of 512

struct v8 { float f[8]; };

__device__ __forceinline__ v8 ldg_v8(const float* p) {
    v8 r;
    asm volatile("ld.global.nc.v8.f32 {%0,%1,%2,%3,%4,%5,%6,%7}, [%8];"
                 : "=f"(r.f[0]), "=f"(r.f[1]), "=f"(r.f[2]), "=f"(r.f[3]),
                   "=f"(r.f[4]), "=f"(r.f[5]), "=f"(r.f[6]), "=f"(r.f[7])
                 : "l"(p));
    return r;
}

__device__ __forceinline__ void stg_v8(float* p, const v8& v) {
    asm volatile("st.global.v8.f32 [%0], {%1,%2,%3,%4,%5,%6,%7,%8};"
                 :: "l"(p),
                    "f"(v.f[0]), "f"(v.f[1]), "f"(v.f[2]), "f"(v.f[3]),
                    "f"(v.f[4]), "f"(v.f[5]), "f"(v.f[6]), "f"(v.f[7])
                 : "memory");
}

__global__ void __launch_bounds__(THREADS)
svdropout2d_kernel(const float* __restrict__ x,
                   const float* __restrict__ log_sigma,
                   float* __restrict__ out)
{
    const float E = 2.71828182845904523536f;

    const long long i = (long long)blockIdx.x * THREADS + threadIdx.x;  // v8 idx

    // Same column for both elements (stride % 512 == 0): one scale set.
    const int c = (int)(i & (V8_PER_ROW - 1));

    v8 s;
    #pragma unroll
    for (int j = 0; j < 8; ++j) {
        float ls = __ldg(&log_sigma[c * 8 + j]);
        s.f[j] = (ls < 1.0f) ? E : 1.0f;
    }

    // Front-batched, batch depth 2 (the measured optimum), 64B/lane in flight
    v8 v0 = ldg_v8(x + i * 8);
    v8 v1 = ldg_v8(x + (i + NSTRIDE) * 8);

    #pragma unroll
    for (int j = 0; j < 8; ++j) v0.f[j] *= s.f[j];
    #pragma unroll
    for (int j = 0; j < 8; ++j) v1.f[j] *= s.f[j];

    stg_v8(out + i * 8, v0);
    stg_v8(out + (i + NSTRIDE) * 8, v1);
}

extern "C" void kernel_launch(void* const* d_in, const int* in_sizes, int n_in,
                              void* d_out, int out_size)
{
    const float* x  = (const float*)d_in[0];
    const float* ls = (const float*)d_in[1];
    float* out      = (float*)d_out;

    svdropout2d_kernel<<<BLOCKS, THREADS>>>(x, ls, out);
}

// round 15
// speedup vs baseline: 1.0133x; 1.0133x over previous
#include <cuda_runtime.h>

// out[b,f] = x[b,f] * (log_sigma[f] < 1.0f ? e : 1.0f)
// BATCH=65536, N_FEATURES=4096 -> 2^26 float4. Pure HBM stream (2.15 GB).
//
// R15: champion shape (fine-grained, 1024-thr blocks, 2 front-batched
// 128-bit loads = 32B/lane in flight — the measured DRAM optimum) with
// BLOCK-LOCAL pairing: each block owns a contiguous 32KB chunk, thread t
// handles float4s [b*2048 + t] and [b*2048 + t + 1024]. Both loads/stores
// of a warp stay within one 2MB page -> better DRAM row/channel locality
// than the 512MB-apart pairing of R11/R13.
//
// Column invariance: chunk base b*2048 and offset 1024 are both multiples
// of 1024 (VEC4_PER_ROW), so both elements share one column index.

#define N_FEATURES   4096
#define VEC4_PER_ROW (N_FEATURES / 4)            // 1024, power of two
#define TOTAL_VEC4   (65536LL * VEC4_PER_ROW)    // 2^26

#define THREADS  1024
#define BLOCKS   32768                            // 32768 * 2048 = 2^26 exact

__global__ void __launch_bounds__(THREADS)
svdropout2d_kernel(const float4* __restrict__ x,
                   const float4* __restrict__ log_sigma,
                   float4* __restrict__ out)
{
    const float E = 2.71828182845904523536f;

    const long long i = (long long)blockIdx.x * (2 * THREADS) + threadIdx.x;

    // Same column for both elements (2*THREADS and THREADS are multiples
    // of 1024): one scale load.
    const int c = (int)(i & (VEC4_PER_ROW - 1));
    const float4 ls = __ldg(&log_sigma[c]);

    float4 s;
    s.x = (ls.x < 1.0f) ? E : 1.0f;
    s.y = (ls.y < 1.0f) ? E : 1.0f;
    s.z = (ls.z < 1.0f) ? E : 1.0f;
    s.w = (ls.w < 1.0f) ? E : 1.0f;

    // Front-batched independent loads (MLP_p1 = 2), block-local 16KB apart
    float4 v0 = x[i];
    float4 v1 = x[i + THREADS];

    v0.x *= s.x; v0.y *= s.y; v0.z *= s.z; v0.w *= s.w;
    v1.x *= s.x; v1.y *= s.y; v1.z *= s.z; v1.w *= s.w;

    out[i]           = v0;
    out[i + THREADS] = v1;
}

extern "C" void kernel_launch(void* const* d_in, const int* in_sizes, int n_in,
                              void* d_out, int out_size)
{
    const float4* x  = (const float4*)d_in[0];
    const float4* ls = (const float4*)d_in[1];
    float4* out      = (float4*)d_out;

    svdropout2d_kernel<<<BLOCKS, THREADS>>>(x, ls, out);
}